// round 9
// baseline (speedup 1.0000x reference)
#include <cuda_runtime.h>
#include <cuda_fp16.h>
#include <math.h>
#include <stdint.h>

#define HLR   96
#define HWLR  9216
#define HHR   384
#define NQ    147456
#define TR    64                   // GEMM tile rows
#define NT2   (NQ/TR)              // 2304 tiles
#define KPAD  264                  // A smem row pad (fp16 elems)
#define BPAD  40                   // B smem row pad (fp16 elems)
#define FPAD  260                  // h3 fp32 smem row pad
#define A_B   (TR*KPAD*2)          // 33792 bytes per A component
#define B_COMP (256*BPAD*2)        // 20480 bytes per B stage
#define DSM2  (2*A_B + 2*B_COMP)   // 108544

// ---------------- static device scratch ----------------
__device__ float g_b1[64*HWLR];
__device__ float g_b2[64*HWLR];
__device__ float g_feat[64*HWLR];
__device__ float g_H[(size_t)HWLR*384];
__device__ float g_offH[16*256];
__device__ float g_offC[16*64];
__device__ float g_offL[16*64];
__device__ float g_pred[3*NQ];
__device__ int   g_flag[NQ];
__device__ int   g_cnt;
__device__ int   g_qidx[NQ];
__device__ float g_resid[3*NQ];
__device__ __align__(16) __half g_W2h[65536];   // [n][k] fp16
__device__ __align__(16) __half g_W3h[65536];

// ---------------- helpers ----------------
__device__ __forceinline__ uint32_t smem_u32(const void* p){
    uint32_t a;
    asm("{ .reg .u64 t; cvta.to.shared.u64 t, %1; cvt.u32.u64 %0, t; }" : "=r"(a) : "l"(p));
    return a;
}
__device__ __forceinline__ void ldsm4(uint32_t r[4], uint32_t addr){
    asm volatile("ldmatrix.sync.aligned.m8n8.x4.shared.b16 {%0,%1,%2,%3}, [%4];"
        : "=r"(r[0]),"=r"(r[1]),"=r"(r[2]),"=r"(r[3]) : "r"(addr));
}
__device__ __forceinline__ void mma_f16(float& c0, float& c1, float& c2, float& c3,
    const uint32_t a[4], uint32_t b0, uint32_t b1){
    asm volatile("mma.sync.aligned.m16n8k16.row.col.f32.f16.f16.f32 "
        "{%0,%1,%2,%3}, {%4,%5,%6,%7}, {%8,%9}, {%0,%1,%2,%3};"
        : "+f"(c0),"+f"(c1),"+f"(c2),"+f"(c3)
        : "r"(a[0]),"r"(a[1]),"r"(a[2]),"r"(a[3]),"r"(b0),"r"(b1));
}
__device__ __forceinline__ void split2h(float v0, float v1, uint32_t& hi, uint32_t& lo){
    __half h0=__float2half(v0), h1=__float2half(v1);
    float f0=__half2float(h0), f1=__half2float(h1);
    __half l0=__float2half(v0-f0), l1=__float2half(v1-f1);
    hi = (uint32_t)__half_as_ushort(h0) | ((uint32_t)__half_as_ushort(h1)<<16);
    lo = (uint32_t)__half_as_ushort(l0) | ((uint32_t)__half_as_ushort(l1)<<16);
}
__device__ __forceinline__ void cp16(uint32_t dst, const void* src){
    asm volatile("cp.async.cg.shared.global [%0], [%1], 16;" :: "r"(dst), "l"(src));
}

// ---------------- offset precompute + counter reset ----------------
__global__ void precompute_kernel(const float* __restrict__ wh1, const float* __restrict__ bh1,
                                  const float* __restrict__ wc1, const float* __restrict__ bc1,
                                  const float* __restrict__ wl1, const float* __restrict__ bl1,
                                  const float* __restrict__ cell)
{
    int t = threadIdx.x;
    if (t==0) g_cnt = 0;
    float rcy = cell[0]*96.0f, rcx = cell[1]*96.0f;
    float rel[4];
#pragma unroll
    for (int m=0;m<4;m++){
        float cy = -1.0f + (2.0f*(float)m + 1.0f)/384.0f;
        float fy = -1.0f + 1.0f/96.0f;
        rel[m] = (cy - fy)*96.0f;
    }
    for (int m=0;m<16;m++){
        float ry = rel[m>>2], rx = rel[m&3];
        g_offH[m*256+t] = ry*wh1[64*256+t] + rx*wh1[65*256+t]
                        + rcy*wh1[66*256+t] + rcx*wh1[67*256+t] + bh1[t];
        if (t < 64){
            g_offC[m*64+t] = ry*wc1[64*64+t] + rx*wc1[65*64+t]
                           + rcy*wc1[66*64+t] + rcx*wc1[67*64+t] + bc1[t];
            g_offL[m*64+t] = ry*wl1[64*64+t] + rx*wl1[65*64+t]
                           + rcy*wl1[66*64+t] + rcx*wl1[67*64+t] + bl1[t];
        }
    }
}

// ---------------- weight convert to fp16 [n][k] images ----------------
__global__ void wsplit_kernel(const float* __restrict__ wh2, const float* __restrict__ wh3)
{
    int idx = blockIdx.x*256 + threadIdx.x;
    int layer = idx >> 16;
    int e = idx & 65535;
    int k = e >> 8, n = e & 255;
    const float* w = layer ? wh3 : wh2;
    float v = w[k*256 + n];
    if (layer) g_W3h[(uint32_t)n*256u + k] = __float2half(v);
    else       g_W2h[(uint32_t)n*256u + k] = __float2half(v);
}

// ---------------- 3x3 SAME conv; cp.async double-buffered ic chunks ----------------
// grid (96 rows, 4 oc-groups), 256 threads, 16oc x 16 x-groups of 6 px.
// dynamic smem: sIn[2][CH][3][104] then sWall[16][IC][9]
template<int IC, bool RELU>
__global__ __launch_bounds__(256) void conv3x3_kernel(
    const float* __restrict__ in, const float* __restrict__ w,
    const float* __restrict__ bias, float* __restrict__ out)
{
    constexpr int CH = (IC < 16) ? IC : 16;
    constexpr int NCHUNK = IC / CH;
    extern __shared__ __align__(16) char csm[];
    float* sIn   = (float*)csm;                                  // [((b*CH+ic)*3+ry)*104 + x]
    float* sWall = (float*)(csm + (size_t)2*CH*3*104*4);         // [(o*IC+ic)*9 + t]

    const int y   = blockIdx.x;
    const int ocg = blockIdx.y;
    const int tid = threadIdx.x;
    const int ol  = tid >> 4;
    const int oc  = ocg*16 + ol;
    const int x0  = (tid & 15) * 6;

    // zero pads + invalid rows (both buffers)
    for (int i=tid; i<2*CH*3; i+=256){
        int b = i/(CH*3), rr = i - b*(CH*3);
        int ic = rr/3, ry = rr - ic*3;
        float* row = sIn + (((b*CH+ic)*3+ry)*104);
        row[3] = 0.0f; row[100] = 0.0f;
        int yy = y + ry - 1;
        if (yy < 0 || yy >= 96){
            for (int x=4; x<100; x++) row[x] = 0.0f;
        }
    }

    // one-shot weight preload (contiguous for this ocg)
    {
        const float* wsrc = w + (size_t)ocg*16*IC*9;
        int nq4 = (16*IC*9) >> 2;
        for (int i=tid; i<nq4; i+=256)
            cp16(smem_u32(sWall + i*4), wsrc + i*4);
    }
    // stage chunk 0 into buf 0
    {
        for (int i=tid; i<CH*3*24; i+=256){
            int ic = i/72, r = i - ic*72, ry = r/24, c4 = r - ry*24;
            int yy = y + ry - 1;
            if (yy>=0 && yy<96)
                cp16(smem_u32(sIn + ((ic*3+ry)*104) + 4 + c4*4),
                     in + (size_t)ic*HWLR + yy*96 + c4*4);
        }
        asm volatile("cp.async.commit_group;");
    }

    float acc[6];
#pragma unroll
    for (int j=0;j<6;j++) acc[j]=0.0f;

    for (int c=0; c<NCHUNK; c++){
        __syncthreads();   // prior compute done before overwriting old buffer
        if (c+1 < NCHUNK){
            int b = (c+1)&1, c0 = (c+1)*CH;
            for (int i=tid; i<CH*3*24; i+=256){
                int ic = i/72, r = i - ic*72, ry = r/24, c4 = r - ry*24;
                int yy = y + ry - 1;
                if (yy>=0 && yy<96)
                    cp16(smem_u32(sIn + (((b*CH+ic)*3+ry)*104) + 4 + c4*4),
                         in + (size_t)(c0+ic)*HWLR + yy*96 + c4*4);
            }
            asm volatile("cp.async.commit_group;");
            asm volatile("cp.async.wait_group 1;");
        } else {
            asm volatile("cp.async.wait_group 0;");
        }
        __syncthreads();

        const int b = c&1, cc0 = c*CH;
#pragma unroll 2
        for (int ic=0; ic<CH; ic++){
            const float* r0p = sIn + (((b*CH+ic)*3+0)*104) + x0 + 3;
            const float* r1p = r0p + 104;
            const float* r2p = r1p + 104;
            float r0[8],r1[8],r2[8];
#pragma unroll
            for (int d=0;d<8;d++){ r0[d]=r0p[d]; r1[d]=r1p[d]; r2[d]=r2p[d]; }
            const float* wp = sWall + ((ol*IC + cc0 + ic)*9);
            float w00=wp[0], w01=wp[1], w02=wp[2];
            float w10=wp[3], w11=wp[4], w12=wp[5];
            float w20=wp[6], w21=wp[7], w22=wp[8];
#pragma unroll
            for (int j=0;j<6;j++){
                acc[j] += w00*r0[j]+w01*r0[j+1]+w02*r0[j+2]
                        + w10*r1[j]+w11*r1[j+1]+w12*r1[j+2]
                        + w20*r2[j]+w21*r2[j+1]+w22*r2[j+2];
            }
        }
    }
    float b = __ldg(bias+oc);
#pragma unroll
    for (int j=0;j<6;j++){
        float v = acc[j]+b;
        if (RELU) v = fmaxf(v,0.0f);
        out[oc*HWLR + y*96 + x0 + j] = v;
    }
}

// ---------------- front GEMM: g_H[p][384] = feat[p][64] x [wc1|wl1|wh1] ----------------
__global__ __launch_bounds__(256) void front_kernel(
    const float* __restrict__ wc1, const float* __restrict__ wl1, const float* __restrict__ wh1)
{
    __shared__ float sF[64][25];
    __shared__ float sW[16][385];
    const int tid = threadIdx.x;
    const int P0  = blockIdx.x*24;
    const int txp = tid & 3;
    const int txc = tid >> 2;

    for (int i=tid; i<64*24; i+=256){
        int c = i/24, pl = i - c*24;
        sF[c][pl] = g_feat[c*HWLR + P0 + pl];
    }

    float acc[6][6];
#pragma unroll
    for (int i=0;i<6;i++)
#pragma unroll
        for (int j=0;j<6;j++) acc[i][j]=0.0f;

    for (int c0=0; c0<64; c0+=16){
        __syncthreads();
        for (int i=tid; i<16*384; i+=256){
            int cc = i/384, n = i - cc*384;
            int c = c0 + cc;
            float w;
            if (n < 64)        w = wc1[c*64 + n];
            else if (n < 128)  w = wl1[c*64 + (n-64)];
            else               w = wh1[c*256 + (n-128)];
            sW[cc][n] = w;
        }
        __syncthreads();
#pragma unroll
        for (int cc=0; cc<16; cc++){
            float f[6], w[6];
#pragma unroll
            for (int j=0;j<6;j++) f[j] = sF[c0+cc][txp*6+j];
#pragma unroll
            for (int i=0;i<6;i++) w[i] = sW[cc][txc*6+i];
#pragma unroll
            for (int i=0;i<6;i++)
#pragma unroll
                for (int j=0;j<6;j++) acc[i][j] += w[i]*f[j];
        }
    }
#pragma unroll
    for (int j=0;j<6;j++)
#pragma unroll
        for (int i=0;i<6;i++)
            g_H[(size_t)(P0 + txp*6 + j)*384 + txc*6 + i] = acc[i][j];
}

// ---------------- mlpB: classify/light/compact; 4 px per block ----------------
__global__ __launch_bounds__(256) void mlpB_kernel(
    const float* __restrict__ lr,
    const float* __restrict__ wc2, const float* __restrict__ bc2,
    const float* __restrict__ wl2, const float* __restrict__ bl2,
    float* __restrict__ out, int out_size)
{
    __shared__ float sHc[4][64];
    __shared__ float sHl[4][64];
    __shared__ float sPredL[4][16][3];
    __shared__ int sFlag[4][16];
    __shared__ int sInv[4][16];
    __shared__ int sMcount[4];
    __shared__ int sBase[4];

    const int tid = threadIdx.x;
    const int p0  = blockIdx.x*4;

    {
        int pp = tid>>6, c = tid&63;
        sHc[pp][c] = g_H[(size_t)(p0+pp)*384 + c];
        sHl[pp][c] = g_H[(size_t)(p0+pp)*384 + 64 + c];
    }
    __syncthreads();

    {
        int wid = tid>>5, lane = tid&31;
#pragma unroll
        for (int i=0;i<8;i++){
            int qq = wid*8 + i;
            int pp = qq>>4, m = qq&15;
            float l0=0,l1=0,q0=0,q1=0,q2=0;
#pragma unroll
            for (int hh=0;hh<2;hh++){
                int t = lane + hh*32;
                float hc = fmaxf(sHc[pp][t] + g_offC[m*64+t], 0.0f);
                l0 += hc*__ldg(&wc2[t*2+0]);
                l1 += hc*__ldg(&wc2[t*2+1]);
                float hl = fmaxf(sHl[pp][t] + g_offL[m*64+t], 0.0f);
                q0 += hl*__ldg(&wl2[t*3+0]);
                q1 += hl*__ldg(&wl2[t*3+1]);
                q2 += hl*__ldg(&wl2[t*3+2]);
            }
#pragma unroll
            for (int o=16;o>0;o>>=1){
                l0+=__shfl_xor_sync(0xffffffffu,l0,o);
                l1+=__shfl_xor_sync(0xffffffffu,l1,o);
                q0+=__shfl_xor_sync(0xffffffffu,q0,o);
                q1+=__shfl_xor_sync(0xffffffffu,q1,o);
                q2+=__shfl_xor_sync(0xffffffffu,q2,o);
            }
            if (lane==0){
                l0 += __ldg(&bc2[0]); l1 += __ldg(&bc2[1]);
                sFlag[pp][m] = (l1 > l0) ? 1 : 0;
                sPredL[pp][m][0] = q0 + __ldg(&bl2[0]);
                sPredL[pp][m][1] = q1 + __ldg(&bl2[1]);
                sPredL[pp][m][2] = q2 + __ldg(&bl2[2]);
            }
        }
    }
    __syncthreads();

    if (tid < 4){
        int c=0;
        for (int m=0;m<16;m++){
            sInv[tid][m] = -1;
            if (sFlag[tid][m]){ sInv[tid][m]=c; c++; }
        }
        sMcount[tid] = c;
    }
    __syncthreads();
    if (tid==0){
        int tot = sMcount[0]+sMcount[1]+sMcount[2]+sMcount[3];
        int b = tot ? atomicAdd(&g_cnt, tot) : 0;
        sBase[0]=b;
        sBase[1]=b+sMcount[0];
        sBase[2]=sBase[1]+sMcount[1];
        sBase[3]=sBase[2]+sMcount[2];
    }
    __syncthreads();

    if (tid < 64){
        int pp = tid>>4, mm = tid&15;
        int p = p0+pp, py = p/96, px = p - py*96;
        int r = py*4 + (mm>>2), s = px*4 + (mm&3);
        int q = r*HHR + s;
        g_flag[q] = sFlag[pp][mm];
        if (out_size >= 4*NQ) out[3*NQ + q] = (float)sFlag[pp][mm];
    }

    if (tid < 192){
        int pp = tid/48, r3 = tid - pp*48;
        int m = r3/3, j = r3 - m*3;
        int p = p0+pp, py = p/96, px = p - py*96;
        int r = py*4 + (m>>2), s = px*4 + (m&3);
        int q = r*HHR + s;
        float cy = -1.0f + (2.0f*(float)r + 1.0f)/384.0f;
        float cx = -1.0f + (2.0f*(float)s + 1.0f)/384.0f;
        float fy = fminf(fmaxf((cy+1.0f)*48.0f - 0.5f, 0.0f), 95.0f);
        float fx = fminf(fmaxf((cx+1.0f)*48.0f - 0.5f, 0.0f), 95.0f);
        float y0f = floorf(fy), x0f = floorf(fx);
        float wy = fy - y0f, wx = fx - x0f;
        int y0 = (int)y0f, x0 = (int)x0f;
        int y1 = min(y0+1,95), x1 = min(x0+1,95);
        const float* img = lr + j*HWLR;
        float v00=__ldg(&img[y0*96+x0]), v01=__ldg(&img[y0*96+x1]);
        float v10=__ldg(&img[y1*96+x0]), v11=__ldg(&img[y1*96+x1]);
        float resid = v00*(1.0f-wy)*(1.0f-wx) + v01*(1.0f-wy)*wx
                    + v10*wy*(1.0f-wx)       + v11*wy*wx;
        if (sFlag[pp][m]==0){
            g_pred[j*NQ + q] = sPredL[pp][m][j] + resid;
        } else {
            int slot = sBase[pp] + sInv[pp][m];
            g_resid[slot*3 + j] = resid;
            if (j==0) g_qidx[slot] = q;
        }
    }
}

// ---------------- B stage (fp16) via cp.async ----------------
__device__ __forceinline__ void stage_B(int tid, uint32_t bbase,
    const __half* __restrict__ Wh, int kc)
{
    for (int i=tid;i<1024;i+=256){
        int n=i>>2, c4=i&3;
        cp16(bbase + (uint32_t)n*(BPAD*2) + (uint32_t)c4*16, Wh + n*256 + kc*32 + c4*8);
    }
    asm volatile("cp.async.commit_group;");
}

// ---------------- GEMM: heavy layers 1(build)+2+3+4; layer2 2-product, layer3 1-product ----------------
__global__ __launch_bounds__(256, 2) void gemm_kernel(
    const float* __restrict__ bh2, const float* __restrict__ bh3,
    const float* __restrict__ wh4, const float* __restrict__ bh4)
{
    extern __shared__ unsigned char sm[];
    __shared__ float sB2[256], sB3[256], sBh4[4];
    __shared__ int sQ[TR];
    __shared__ int s_cnt;

    const int tid = threadIdx.x, wid = tid>>5, lane = tid&31;
    if (tid==0) s_cnt = g_cnt;
    __syncthreads();
    const int cnt  = s_cnt;
    const int base = blockIdx.x*TR;
    if (base >= cnt) return;
    const int valid = min(TR, cnt - base);

    sB2[tid]=__ldg(&bh2[tid]); sB3[tid]=__ldg(&bh3[tid]);
    if (tid<3) sBh4[tid]=__ldg(&bh4[tid]);
    if (tid < valid) sQ[tid] = g_qidx[base+tid];
    __syncthreads();

    // build A (h1 hi/lo fp16) from g_H + g_offH; offsets held in registers
    {
        float offv[16];
#pragma unroll
        for (int m=0;m<16;m++) offv[m] = g_offH[m*256+tid];
        for (int i=0;i<valid;i++){
            int q = sQ[i];
            int r = q/HHR, s = q - r*HHR;
            int m = (r&3)*4 + (s&3);
            int p = (r>>2)*96 + (s>>2);
            float v = fmaxf(g_H[(size_t)p*384 + 128 + tid] + offv[m], 0.0f);
            __half h = __float2half(v);
            __half l = __float2half(v - __half2float(h));
            uint32_t hu = __half_as_ushort(h), lu = __half_as_ushort(l);
            uint32_t hn = __shfl_down_sync(0xffffffffu, hu, 1);
            uint32_t ln = __shfl_down_sync(0xffffffffu, lu, 1);
            if (!(lane&1)){
                *(uint32_t*)(sm + i*(KPAD*2) + tid*2)       = hu | (hn<<16);
                *(uint32_t*)(sm + A_B + i*(KPAD*2) + tid*2) = lu | (ln<<16);
            }
        }
    }

    const int wm = wid & 1;      // 2 row groups of 32
    const int wn = wid >> 1;     // 4 col groups of 64
    const uint32_t smA = smem_u32(sm);
    const uint32_t smB = smA + 2*A_B;

    float acc[64];
#pragma unroll
    for (int i=0;i<64;i++) acc[i]=0.0f;

    stage_B(tid, smB, g_W2h, 0);

    for (int idx=0; idx<16; idx++){
        if (idx < 15){
            int nx = idx+1;
            stage_B(tid, smB + (uint32_t)(nx&1)*B_COMP, (nx&8)?g_W3h:g_W2h, nx&7);
            asm volatile("cp.async.wait_group 1;");
        } else {
            asm volatile("cp.async.wait_group 0;");
        }
        __syncthreads();

        const int kc = idx & 7;
        const bool useLo = (idx < 8);     // layer2: 2 products; layer3: hi only
        const uint32_t bB = smB + (uint32_t)(idx&1)*B_COMP;
#pragma unroll
        for (int kk=0; kk<32; kk+=16){
            uint32_t ah[2][4], al[2][4];
#pragma unroll
            for (int mt=0; mt<2; mt++){
                int r = wm*32 + mt*16 + (lane&7) + ((lane>>3)&1)*8;
                int kcol = kc*32 + kk + (lane>>4)*8;
                uint32_t aAddr = smA + (uint32_t)(r*KPAD + kcol)*2u;
                ldsm4(ah[mt], aAddr);
                if (useLo) ldsm4(al[mt], aAddr + A_B);
            }
#pragma unroll
            for (int nt4=0; nt4<4; nt4++){
                int n = wn*64 + nt4*16 + (lane>>4)*8 + (lane&7);
                int kl = kk + ((lane>>3)&1)*8;
                uint32_t bh[4];
                ldsm4(bh, bB + (uint32_t)(n*BPAD + kl)*2u);
#pragma unroll
                for (int mt=0; mt<2; mt++){
#pragma unroll
                    for (int s2=0; s2<2; s2++){
                        const int ci = (mt*8 + nt4*2 + s2)*4;
                        mma_f16(acc[ci],acc[ci+1],acc[ci+2],acc[ci+3], ah[mt], bh[s2*2], bh[s2*2+1]);
                        if (useLo)
                            mma_f16(acc[ci],acc[ci+1],acc[ci+2],acc[ci+3], al[mt], bh[s2*2], bh[s2*2+1]);
                    }
                }
            }
        }
        __syncthreads();

        if (idx == 7){
            // h2 = relu(D + bh2) -> fp16 hi/lo back into A smem
#pragma unroll
            for (int mt=0; mt<2; mt++){
#pragma unroll
                for (int nt=0; nt<8; nt++){
                    const int ci = (mt*8 + nt)*4;
                    int rowA = wm*32 + mt*16 + (lane>>2);
                    int col0 = wn*64 + nt*8 + (lane&3)*2;
                    uint32_t hi, lo;
                    split2h(fmaxf(acc[ci+0]+sB2[col0],0.0f), fmaxf(acc[ci+1]+sB2[col0+1],0.0f), hi, lo);
                    *(uint32_t*)(sm + rowA*(KPAD*2) + col0*2) = hi;
                    *(uint32_t*)(sm + A_B + rowA*(KPAD*2) + col0*2) = lo;
                    split2h(fmaxf(acc[ci+2]+sB2[col0],0.0f), fmaxf(acc[ci+3]+sB2[col0+1],0.0f), hi, lo);
                    *(uint32_t*)(sm + (rowA+8)*(KPAD*2) + col0*2) = hi;
                    *(uint32_t*)(sm + A_B + (rowA+8)*(KPAD*2) + col0*2) = lo;
                    acc[ci+0]=0.0f; acc[ci+1]=0.0f; acc[ci+2]=0.0f; acc[ci+3]=0.0f;
                }
            }
            __syncthreads();
        }
    }

    // h3 = relu(D + bh3) -> fp32 smem, then 256->3 reduction
    float* sF = (float*)sm;
#pragma unroll
    for (int mt=0; mt<2; mt++){
#pragma unroll
        for (int nt=0; nt<8; nt++){
            const int ci = (mt*8 + nt)*4;
            int rowA = wm*32 + mt*16 + (lane>>2);
            int col0 = wn*64 + nt*8 + (lane&3)*2;
            sF[rowA*FPAD + col0]       = fmaxf(acc[ci+0]+sB3[col0],   0.0f);
            sF[rowA*FPAD + col0+1]     = fmaxf(acc[ci+1]+sB3[col0+1], 0.0f);
            sF[(rowA+8)*FPAD + col0]   = fmaxf(acc[ci+2]+sB3[col0],   0.0f);
            sF[(rowA+8)*FPAD + col0+1] = fmaxf(acc[ci+3]+sB3[col0+1], 0.0f);
        }
    }
    __syncthreads();

    {
        int row = tid>>2, part = tid&3;
        const float4* rp = (const float4*)(sF + row*FPAD + part*64);
        float a0=0,a1=0,a2=0;
#pragma unroll
        for (int j=0;j<16;j++){
            float4 v = rp[j];
            int cb = part*64 + j*4;
            a0 += v.x*__ldg(&wh4[cb*3+0]) + v.y*__ldg(&wh4[(cb+1)*3+0]) + v.z*__ldg(&wh4[(cb+2)*3+0]) + v.w*__ldg(&wh4[(cb+3)*3+0]);
            a1 += v.x*__ldg(&wh4[cb*3+1]) + v.y*__ldg(&wh4[(cb+1)*3+1]) + v.z*__ldg(&wh4[(cb+2)*3+1]) + v.w*__ldg(&wh4[(cb+3)*3+1]);
            a2 += v.x*__ldg(&wh4[cb*3+2]) + v.y*__ldg(&wh4[(cb+1)*3+2]) + v.z*__ldg(&wh4[(cb+2)*3+2]) + v.w*__ldg(&wh4[(cb+3)*3+2]);
        }
#pragma unroll
        for (int o=1;o<4;o<<=1){
            a0 += __shfl_xor_sync(0xffffffffu, a0, o);
            a1 += __shfl_xor_sync(0xffffffffu, a1, o);
            a2 += __shfl_xor_sync(0xffffffffu, a2, o);
        }
        if (part==0 && row < valid){
            int slot = base + row;
            int q = sQ[row];
            g_pred[       q] = a0 + sBh4[0] + g_resid[slot*3+0];
            g_pred[  NQ + q] = a1 + sBh4[1] + g_resid[slot*3+1];
            g_pred[2*NQ + q] = a2 + sBh4[2] + g_resid[slot*3+2];
        }
    }
}

// ---------------- refinement: 16x16 tile + halo in smem ----------------
__global__ __launch_bounds__(256) void refine_kernel(float* __restrict__ out)
{
    __shared__ float sp[3][18][18];
    __shared__ int   sf[18][18];
    const int tid = threadIdx.x;
    const int bx = blockIdx.x*16, by = blockIdx.y*16;

    for (int i=tid; i<324; i+=256){
        int lr_ = i/18, lc = i - lr_*18;
        int gr = min(max(by + lr_ - 1, 0), HHR-1);
        int gc = min(max(bx + lc - 1, 0), HHR-1);
        int qq = gr*HHR + gc;
        sf[lr_][lc]    = g_flag[qq];
        sp[0][lr_][lc] = g_pred[qq];
        sp[1][lr_][lc] = g_pred[NQ+qq];
        sp[2][lr_][lc] = g_pred[2*NQ+qq];
    }
    __syncthreads();

    const int ty = tid>>4, tx = tid&15;
    const int r = by+ty, s = bx+tx;
    const int q = r*HHR + s;
    float p0 = sp[0][ty+1][tx+1], p1 = sp[1][ty+1][tx+1], p2 = sp[2][ty+1][tx+1];
    if (r>0 && r<HHR-1 && s>0 && s<HHR-1 && sf[ty+1][tx+1]==0){
        int fs = 0;
#pragma unroll
        for (int dy=0;dy<3;dy++)
#pragma unroll
            for (int dx=0;dx<3;dx++)
                fs += sf[ty+dy][tx+dx];
        if (fs > 0){
            float s0=0,s1=0,s2=0;
#pragma unroll
            for (int dy=0;dy<3;dy++)
#pragma unroll
                for (int dx=0;dx<3;dx++){
                    s0 += sp[0][ty+dy][tx+dx];
                    s1 += sp[1][ty+dy][tx+dx];
                    s2 += sp[2][ty+dy][tx+dx];
                }
            p0 = s0/9.0f; p1 = s1/9.0f; p2 = s2/9.0f;
        }
    }
    out[q*3+0] = p0;
    out[q*3+1] = p1;
    out[q*3+2] = p2;
}

// ---------------- launch ----------------
extern "C" void kernel_launch(void* const* d_in, const int* in_sizes, int n_in,
                              void* d_out, int out_size)
{
    (void)in_sizes; (void)n_in;
    const float* lr  =(const float*)d_in[0];
    const float* cell=(const float*)d_in[2];
    const float* ew1 =(const float*)d_in[3];
    const float* eb1 =(const float*)d_in[4];
    const float* ew2 =(const float*)d_in[5];
    const float* eb2 =(const float*)d_in[6];
    const float* ew3 =(const float*)d_in[7];
    const float* eb3 =(const float*)d_in[8];
    const float* wh1 =(const float*)d_in[9];
    const float* bh1 =(const float*)d_in[10];
    const float* wh2 =(const float*)d_in[11];
    const float* bh2 =(const float*)d_in[12];
    const float* wh3 =(const float*)d_in[13];
    const float* bh3 =(const float*)d_in[14];
    const float* wh4 =(const float*)d_in[15];
    const float* bh4 =(const float*)d_in[16];
    const float* wl1 =(const float*)d_in[17];
    const float* bl1 =(const float*)d_in[18];
    const float* wl2 =(const float*)d_in[19];
    const float* bl2 =(const float*)d_in[20];
    const float* wc1 =(const float*)d_in[21];
    const float* bc1 =(const float*)d_in[22];
    const float* wc2 =(const float*)d_in[23];
    const float* bc2 =(const float*)d_in[24];
    float* out = (float*)d_out;

    float *b1, *b2, *feat;
    cudaGetSymbolAddress((void**)&b1,   g_b1);
    cudaGetSymbolAddress((void**)&b2,   g_b2);
    cudaGetSymbolAddress((void**)&feat, g_feat);

    // dynamic smem sizes for convs
    const int sm3  = 2*3*3*104*4  + 16*3*9*4;    // 9216
    const int sm64 = 2*16*3*104*4 + 16*64*9*4;   // 76800
    cudaFuncSetAttribute(conv3x3_kernel<3 ,true >, cudaFuncAttributeMaxDynamicSharedMemorySize, sm3);
    cudaFuncSetAttribute(conv3x3_kernel<64,true >, cudaFuncAttributeMaxDynamicSharedMemorySize, sm64);
    cudaFuncSetAttribute(conv3x3_kernel<64,false>, cudaFuncAttributeMaxDynamicSharedMemorySize, sm64);
    cudaFuncSetAttribute(gemm_kernel, cudaFuncAttributeMaxDynamicSharedMemorySize, DSM2);

    precompute_kernel<<<1,256>>>(wh1,bh1,wc1,bc1,wl1,bl1,cell);
    wsplit_kernel<<<512,256>>>(wh2, wh3);
    conv3x3_kernel<3 ,true ><<<dim3(96,4),256,sm3 >>>(lr, ew1, eb1, b1);
    conv3x3_kernel<64,true ><<<dim3(96,4),256,sm64>>>(b1, ew2, eb2, b2);
    conv3x3_kernel<64,false><<<dim3(96,4),256,sm64>>>(b2, ew3, eb3, feat);
    front_kernel<<<384,256>>>(wc1, wl1, wh1);
    mlpB_kernel<<<2304,256>>>(lr, wc2, bc2, wl2, bl2, out, out_size);
    gemm_kernel<<<NT2,256,DSM2>>>(bh2, bh3, wh4, bh4);
    refine_kernel<<<dim3(24,24),256>>>(out);
}

// round 10
// speedup vs baseline: 1.0837x; 1.0837x over previous
#include <cuda_runtime.h>
#include <cuda_fp16.h>
#include <math.h>
#include <stdint.h>

#define HLR   96
#define HWLR  9216
#define HHR   384
#define NQ    147456
#define TR    64                   // GEMM tile rows
#define NT2   (NQ/TR)              // 2304 tiles
#define KPAD  264                  // A smem row pad (fp16 elems)
#define BPAD  40                   // B smem row pad (fp16 elems)
#define FPAD  260                  // h3 fp32 smem row pad
#define A_B   (TR*KPAD*2)          // 33792 bytes per A component
#define B_COMP (256*BPAD*2)        // 20480 bytes per B stage
#define DSM2  (2*A_B + 2*B_COMP)   // 108544

// ---------------- static device scratch ----------------
__device__ float g_b1[64*HWLR];
__device__ float g_b2[64*HWLR];
__device__ float g_feat[64*HWLR];
__device__ float g_H[(size_t)HWLR*384];
__device__ float g_offH[16*256];
__device__ float g_offC[16*64];
__device__ float g_offL[16*64];
__device__ float g_pred[3*NQ];
__device__ int   g_flag[NQ];
__device__ int   g_cnt;
__device__ int   g_qidx[NQ];
__device__ float g_resid[3*NQ];
__device__ __align__(16) __half g_W2h[65536];   // [n][k] fp16
__device__ __align__(16) __half g_W3h[65536];

// ---------------- helpers ----------------
__device__ __forceinline__ uint32_t smem_u32(const void* p){
    uint32_t a;
    asm("{ .reg .u64 t; cvta.to.shared.u64 t, %1; cvt.u32.u64 %0, t; }" : "=r"(a) : "l"(p));
    return a;
}
__device__ __forceinline__ void ldsm4(uint32_t r[4], uint32_t addr){
    asm volatile("ldmatrix.sync.aligned.m8n8.x4.shared.b16 {%0,%1,%2,%3}, [%4];"
        : "=r"(r[0]),"=r"(r[1]),"=r"(r[2]),"=r"(r[3]) : "r"(addr));
}
__device__ __forceinline__ void mma_f16(float& c0, float& c1, float& c2, float& c3,
    const uint32_t a[4], uint32_t b0, uint32_t b1){
    asm volatile("mma.sync.aligned.m16n8k16.row.col.f32.f16.f16.f32 "
        "{%0,%1,%2,%3}, {%4,%5,%6,%7}, {%8,%9}, {%0,%1,%2,%3};"
        : "+f"(c0),"+f"(c1),"+f"(c2),"+f"(c3)
        : "r"(a[0]),"r"(a[1]),"r"(a[2]),"r"(a[3]),"r"(b0),"r"(b1));
}
__device__ __forceinline__ void split2h(float v0, float v1, uint32_t& hi, uint32_t& lo){
    __half h0=__float2half(v0), h1=__float2half(v1);
    float f0=__half2float(h0), f1=__half2float(h1);
    __half l0=__float2half(v0-f0), l1=__float2half(v1-f1);
    hi = (uint32_t)__half_as_ushort(h0) | ((uint32_t)__half_as_ushort(h1)<<16);
    lo = (uint32_t)__half_as_ushort(l0) | ((uint32_t)__half_as_ushort(l1)<<16);
}
__device__ __forceinline__ void cp16(uint32_t dst, const void* src){
    asm volatile("cp.async.cg.shared.global [%0], [%1], 16;" :: "r"(dst), "l"(src));
}

// ---------------- offset precompute + counter reset ----------------
__global__ void precompute_kernel(const float* __restrict__ wh1, const float* __restrict__ bh1,
                                  const float* __restrict__ wc1, const float* __restrict__ bc1,
                                  const float* __restrict__ wl1, const float* __restrict__ bl1,
                                  const float* __restrict__ cell)
{
    int t = threadIdx.x;
    if (t==0) g_cnt = 0;
    float rcy = cell[0]*96.0f, rcx = cell[1]*96.0f;
    float rel[4];
#pragma unroll
    for (int m=0;m<4;m++){
        float cy = -1.0f + (2.0f*(float)m + 1.0f)/384.0f;
        float fy = -1.0f + 1.0f/96.0f;
        rel[m] = (cy - fy)*96.0f;
    }
    for (int m=0;m<16;m++){
        float ry = rel[m>>2], rx = rel[m&3];
        g_offH[m*256+t] = ry*wh1[64*256+t] + rx*wh1[65*256+t]
                        + rcy*wh1[66*256+t] + rcx*wh1[67*256+t] + bh1[t];
        if (t < 64){
            g_offC[m*64+t] = ry*wc1[64*64+t] + rx*wc1[65*64+t]
                           + rcy*wc1[66*64+t] + rcx*wc1[67*64+t] + bc1[t];
            g_offL[m*64+t] = ry*wl1[64*64+t] + rx*wl1[65*64+t]
                           + rcy*wl1[66*64+t] + rcx*wl1[67*64+t] + bl1[t];
        }
    }
}

// ---------------- weight convert to fp16 [n][k] images ----------------
__global__ void wsplit_kernel(const float* __restrict__ wh2, const float* __restrict__ wh3)
{
    int idx = blockIdx.x*256 + threadIdx.x;
    int layer = idx >> 16;
    int e = idx & 65535;
    int k = e >> 8, n = e & 255;
    const float* w = layer ? wh3 : wh2;
    float v = w[k*256 + n];
    if (layer) g_W3h[(uint32_t)n*256u + k] = __float2half(v);
    else       g_W2h[(uint32_t)n*256u + k] = __float2half(v);
}

// ---------------- 3x3 SAME conv; double-buffered input AND weight chunks ----------------
// grid (96 rows, 4 oc-groups), 256 threads, 16oc x 16 x-groups of 6 px.
// dyn smem: sIn[2][CH][3][104] then sW[2][16][CH][9]
template<int IC, bool RELU>
__global__ __launch_bounds__(256) void conv3x3_kernel(
    const float* __restrict__ in, const float* __restrict__ w,
    const float* __restrict__ bias, float* __restrict__ out)
{
    constexpr int CH = (IC < 16) ? IC : 16;
    constexpr int NCHUNK = IC / CH;
    constexpr int WCH = 16*CH*9;                         // floats per weight chunk
    extern __shared__ __align__(16) char csm[];
    float* sIn = (float*)csm;                            // [((b*CH+ic)*3+ry)*104 + x]
    float* sW  = (float*)(csm + (size_t)2*CH*3*104*4);   // [b][o][ic][9]

    const int y   = blockIdx.x;
    const int ocg = blockIdx.y;
    const int tid = threadIdx.x;
    const int ol  = tid >> 4;
    const int oc  = ocg*16 + ol;
    const int x0  = (tid & 15) * 6;

    // zero pads + oob rows (both buffers)
    for (int i=tid; i<2*CH*3; i+=256){
        int b = i/(CH*3), rr = i - b*(CH*3);
        int ic = rr/3, ry = rr - ic*3;
        float* row = sIn + (((b*CH+ic)*3+ry)*104);
        row[3] = 0.0f; row[100] = 0.0f;
        int yy = y + ry - 1;
        if (yy < 0 || yy >= 96){
            for (int x=4; x<100; x++) row[x] = 0.0f;
        }
    }

    // ---- staging helpers (inline) ----
    // input chunk cc into buffer b
    auto stage_in = [&](int cc, int b){
        for (int i=tid; i<CH*3*24; i+=256){
            int ic = i/72, r = i - ic*72, ry = r/24, c4 = r - ry*24;
            int yy = y + ry - 1;
            if (yy>=0 && yy<96)
                cp16(smem_u32(sIn + (((b*CH+ic)*3+ry)*104) + 4 + c4*4),
                     in + (size_t)(cc*CH+ic)*HWLR + yy*96 + c4*4);
        }
    };
    auto stage_w = [&](int cc, int b){
        if (IC >= 16){
            // per o: 16 ic x 9 = 144 floats = 36 uint4, 16B-aligned
            for (int i=tid; i<16*36; i+=256){
                int o = i/36, q = i - o*36;
                const float* src = w + ((size_t)(ocg*16+o)*IC + cc*CH)*9 + q*4;
                cp16(smem_u32(sW + b*WCH + o*(CH*9) + q*4), src);
            }
        } else {
            // small: plain copy (ordered by the __syncthreads before compute)
            for (int i=tid; i<WCH; i+=256)
                sW[b*WCH + i] = w[(size_t)ocg*16*IC*9 + i];
        }
    };

    stage_in(0, 0);
    stage_w(0, 0);
    asm volatile("cp.async.commit_group;");

    float acc[6];
#pragma unroll
    for (int j=0;j<6;j++) acc[j]=0.0f;

    for (int c=0; c<NCHUNK; c++){
        __syncthreads();                    // prior compute done before buffer reuse
        if (c+1 < NCHUNK){
            int b = (c+1)&1;
            stage_in(c+1, b);
            stage_w(c+1, b);
            asm volatile("cp.async.commit_group;");
            asm volatile("cp.async.wait_group 1;");
        } else {
            asm volatile("cp.async.wait_group 0;");
        }
        __syncthreads();

        const int b = c&1;
#pragma unroll 2
        for (int ic=0; ic<CH; ic++){
            const float* r0p = sIn + (((b*CH+ic)*3+0)*104) + x0 + 3;
            const float* r1p = r0p + 104;
            const float* r2p = r1p + 104;
            float r0[8],r1[8],r2[8];
#pragma unroll
            for (int d=0;d<8;d++){ r0[d]=r0p[d]; r1[d]=r1p[d]; r2[d]=r2p[d]; }
            const float* wp = sW + b*WCH + (ol*CH + ic)*9;
            float w00=wp[0], w01=wp[1], w02=wp[2];
            float w10=wp[3], w11=wp[4], w12=wp[5];
            float w20=wp[6], w21=wp[7], w22=wp[8];
#pragma unroll
            for (int j=0;j<6;j++){
                acc[j] += w00*r0[j]+w01*r0[j+1]+w02*r0[j+2]
                        + w10*r1[j]+w11*r1[j+1]+w12*r1[j+2]
                        + w20*r2[j]+w21*r2[j+1]+w22*r2[j+2];
            }
        }
    }
    float b = __ldg(bias+oc);
#pragma unroll
    for (int j=0;j<6;j++){
        float v = acc[j]+b;
        if (RELU) v = fmaxf(v,0.0f);
        out[oc*HWLR + y*96 + x0 + j] = v;
    }
}

// ---------------- front GEMM: g_H[p][384] = feat[p][64] x [wc1|wl1|wh1] ----------------
__global__ __launch_bounds__(256) void front_kernel(
    const float* __restrict__ wc1, const float* __restrict__ wl1, const float* __restrict__ wh1)
{
    __shared__ float sF[64][25];
    __shared__ float sW[16][385];
    const int tid = threadIdx.x;
    const int P0  = blockIdx.x*24;
    const int txp = tid & 3;
    const int txc = tid >> 2;

    for (int i=tid; i<64*24; i+=256){
        int c = i/24, pl = i - c*24;
        sF[c][pl] = g_feat[c*HWLR + P0 + pl];
    }

    float acc[6][6];
#pragma unroll
    for (int i=0;i<6;i++)
#pragma unroll
        for (int j=0;j<6;j++) acc[i][j]=0.0f;

    for (int c0=0; c0<64; c0+=16){
        __syncthreads();
        for (int i=tid; i<16*384; i+=256){
            int cc = i/384, n = i - cc*384;
            int c = c0 + cc;
            float w;
            if (n < 64)        w = wc1[c*64 + n];
            else if (n < 128)  w = wl1[c*64 + (n-64)];
            else               w = wh1[c*256 + (n-128)];
            sW[cc][n] = w;
        }
        __syncthreads();
#pragma unroll
        for (int cc=0; cc<16; cc++){
            float f[6], w[6];
#pragma unroll
            for (int j=0;j<6;j++) f[j] = sF[c0+cc][txp*6+j];
#pragma unroll
            for (int i=0;i<6;i++) w[i] = sW[cc][txc*6+i];
#pragma unroll
            for (int i=0;i<6;i++)
#pragma unroll
                for (int j=0;j<6;j++) acc[i][j] += w[i]*f[j];
        }
    }
#pragma unroll
    for (int j=0;j<6;j++)
#pragma unroll
        for (int i=0;i<6;i++)
            g_H[(size_t)(P0 + txp*6 + j)*384 + txc*6 + i] = acc[i][j];
}

// ---------------- mlpB: classify/light/compact; 4 px per block ----------------
__global__ __launch_bounds__(256) void mlpB_kernel(
    const float* __restrict__ lr,
    const float* __restrict__ wc2, const float* __restrict__ bc2,
    const float* __restrict__ wl2, const float* __restrict__ bl2,
    float* __restrict__ out, int out_size)
{
    __shared__ float sHc[4][64];
    __shared__ float sHl[4][64];
    __shared__ float sPredL[4][16][3];
    __shared__ int sFlag[4][16];
    __shared__ int sInv[4][16];
    __shared__ int sMcount[4];
    __shared__ int sBase[4];

    const int tid = threadIdx.x;
    const int p0  = blockIdx.x*4;

    {
        int pp = tid>>6, c = tid&63;
        sHc[pp][c] = g_H[(size_t)(p0+pp)*384 + c];
        sHl[pp][c] = g_H[(size_t)(p0+pp)*384 + 64 + c];
    }
    __syncthreads();

    {
        int wid = tid>>5, lane = tid&31;
#pragma unroll
        for (int i=0;i<8;i++){
            int qq = wid*8 + i;
            int pp = qq>>4, m = qq&15;
            float l0=0,l1=0,q0=0,q1=0,q2=0;
#pragma unroll
            for (int hh=0;hh<2;hh++){
                int t = lane + hh*32;
                float hc = fmaxf(sHc[pp][t] + g_offC[m*64+t], 0.0f);
                l0 += hc*__ldg(&wc2[t*2+0]);
                l1 += hc*__ldg(&wc2[t*2+1]);
                float hl = fmaxf(sHl[pp][t] + g_offL[m*64+t], 0.0f);
                q0 += hl*__ldg(&wl2[t*3+0]);
                q1 += hl*__ldg(&wl2[t*3+1]);
                q2 += hl*__ldg(&wl2[t*3+2]);
            }
#pragma unroll
            for (int o=16;o>0;o>>=1){
                l0+=__shfl_xor_sync(0xffffffffu,l0,o);
                l1+=__shfl_xor_sync(0xffffffffu,l1,o);
                q0+=__shfl_xor_sync(0xffffffffu,q0,o);
                q1+=__shfl_xor_sync(0xffffffffu,q1,o);
                q2+=__shfl_xor_sync(0xffffffffu,q2,o);
            }
            if (lane==0){
                l0 += __ldg(&bc2[0]); l1 += __ldg(&bc2[1]);
                sFlag[pp][m] = (l1 > l0) ? 1 : 0;
                sPredL[pp][m][0] = q0 + __ldg(&bl2[0]);
                sPredL[pp][m][1] = q1 + __ldg(&bl2[1]);
                sPredL[pp][m][2] = q2 + __ldg(&bl2[2]);
            }
        }
    }
    __syncthreads();

    if (tid < 4){
        int c=0;
        for (int m=0;m<16;m++){
            sInv[tid][m] = -1;
            if (sFlag[tid][m]){ sInv[tid][m]=c; c++; }
        }
        sMcount[tid] = c;
    }
    __syncthreads();
    if (tid==0){
        int tot = sMcount[0]+sMcount[1]+sMcount[2]+sMcount[3];
        int b = tot ? atomicAdd(&g_cnt, tot) : 0;
        sBase[0]=b;
        sBase[1]=b+sMcount[0];
        sBase[2]=sBase[1]+sMcount[1];
        sBase[3]=sBase[2]+sMcount[2];
    }
    __syncthreads();

    if (tid < 64){
        int pp = tid>>4, mm = tid&15;
        int p = p0+pp, py = p/96, px = p - py*96;
        int r = py*4 + (mm>>2), s = px*4 + (mm&3);
        int q = r*HHR + s;
        g_flag[q] = sFlag[pp][mm];
        if (out_size >= 4*NQ) out[3*NQ + q] = (float)sFlag[pp][mm];
    }

    if (tid < 192){
        int pp = tid/48, r3 = tid - pp*48;
        int m = r3/3, j = r3 - m*3;
        int p = p0+pp, py = p/96, px = p - py*96;
        int r = py*4 + (m>>2), s = px*4 + (m&3);
        int q = r*HHR + s;
        float cy = -1.0f + (2.0f*(float)r + 1.0f)/384.0f;
        float cx = -1.0f + (2.0f*(float)s + 1.0f)/384.0f;
        float fy = fminf(fmaxf((cy+1.0f)*48.0f - 0.5f, 0.0f), 95.0f);
        float fx = fminf(fmaxf((cx+1.0f)*48.0f - 0.5f, 0.0f), 95.0f);
        float y0f = floorf(fy), x0f = floorf(fx);
        float wy = fy - y0f, wx = fx - x0f;
        int y0 = (int)y0f, x0 = (int)x0f;
        int y1 = min(y0+1,95), x1 = min(x0+1,95);
        const float* img = lr + j*HWLR;
        float v00=__ldg(&img[y0*96+x0]), v01=__ldg(&img[y0*96+x1]);
        float v10=__ldg(&img[y1*96+x0]), v11=__ldg(&img[y1*96+x1]);
        float resid = v00*(1.0f-wy)*(1.0f-wx) + v01*(1.0f-wy)*wx
                    + v10*wy*(1.0f-wx)       + v11*wy*wx;
        if (sFlag[pp][m]==0){
            g_pred[j*NQ + q] = sPredL[pp][m][j] + resid;
        } else {
            int slot = sBase[pp] + sInv[pp][m];
            g_resid[slot*3 + j] = resid;
            if (j==0) g_qidx[slot] = q;
        }
    }
}

// ---------------- B stage (fp16) via cp.async ----------------
__device__ __forceinline__ void stage_B(int tid, uint32_t bbase,
    const __half* __restrict__ Wh, int kc)
{
    for (int i=tid;i<1024;i+=256){
        int n=i>>2, c4=i&3;
        cp16(bbase + (uint32_t)n*(BPAD*2) + (uint32_t)c4*16, Wh + n*256 + kc*32 + c4*8);
    }
    asm volatile("cp.async.commit_group;");
}

// ---------------- GEMM: heavy layers 1(build)+2+3+4; layer2 2-product, layer3 1-product ----------------
__global__ __launch_bounds__(256, 2) void gemm_kernel(
    const float* __restrict__ bh2, const float* __restrict__ bh3,
    const float* __restrict__ wh4, const float* __restrict__ bh4)
{
    extern __shared__ unsigned char sm[];
    __shared__ float sB2[256], sB3[256], sBh4[4];
    __shared__ int sQ[TR], sMi[TR], sPi[TR];
    __shared__ int s_cnt;

    const int tid = threadIdx.x, wid = tid>>5, lane = tid&31;
    if (tid==0) s_cnt = g_cnt;
    __syncthreads();
    const int cnt  = s_cnt;
    const int base = blockIdx.x*TR;
    if (base >= cnt) return;
    const int valid = min(TR, cnt - base);

    sB2[tid]=__ldg(&bh2[tid]); sB3[tid]=__ldg(&bh3[tid]);
    if (tid<3) sBh4[tid]=__ldg(&bh4[tid]);
    if (tid < valid){
        int q = g_qidx[base+tid];
        int r = q/HHR, s = q - r*HHR;
        sQ[tid]  = q;
        sMi[tid] = (r&3)*4 + (s&3);
        sPi[tid] = (r>>2)*96 + (s>>2);
    }
    __syncthreads();

    // build A (h1 hi/lo fp16) from g_H + g_offH (R8-style, no extra register pressure)
    for (int i=0;i<valid;i++){
        int m = sMi[i], p = sPi[i];
        float v = fmaxf(g_H[(size_t)p*384 + 128 + tid] + g_offH[m*256+tid], 0.0f);
        __half h = __float2half(v);
        __half l = __float2half(v - __half2float(h));
        *(unsigned short*)(sm + i*(KPAD*2) + tid*2)       = __half_as_ushort(h);
        *(unsigned short*)(sm + A_B + i*(KPAD*2) + tid*2) = __half_as_ushort(l);
    }

    const int wm = wid & 1;      // 2 row groups of 32
    const int wn = wid >> 1;     // 4 col groups of 64
    const uint32_t smA = smem_u32(sm);
    const uint32_t smB = smA + 2*A_B;

    float acc[64];
#pragma unroll
    for (int i=0;i<64;i++) acc[i]=0.0f;

    stage_B(tid, smB, g_W2h, 0);

    for (int idx=0; idx<16; idx++){
        if (idx < 15){
            int nx = idx+1;
            stage_B(tid, smB + (uint32_t)(nx&1)*B_COMP, (nx&8)?g_W3h:g_W2h, nx&7);
            asm volatile("cp.async.wait_group 1;");
        } else {
            asm volatile("cp.async.wait_group 0;");
        }
        __syncthreads();

        const int kc = idx & 7;
        const bool useLo = (idx < 8);     // layer2: 2 products; layer3: hi only
        const uint32_t bB = smB + (uint32_t)(idx&1)*B_COMP;
#pragma unroll
        for (int kk=0; kk<32; kk+=16){
            uint32_t ah[2][4], al[2][4];
#pragma unroll
            for (int mt=0; mt<2; mt++){
                int r = wm*32 + mt*16 + (lane&7) + ((lane>>3)&1)*8;
                int kcol = kc*32 + kk + (lane>>4)*8;
                uint32_t aAddr = smA + (uint32_t)(r*KPAD + kcol)*2u;
                ldsm4(ah[mt], aAddr);
                if (useLo) ldsm4(al[mt], aAddr + A_B);
            }
#pragma unroll
            for (int nt4=0; nt4<4; nt4++){
                int n = wn*64 + nt4*16 + (lane>>4)*8 + (lane&7);
                int kl = kk + ((lane>>3)&1)*8;
                uint32_t bh[4];
                ldsm4(bh, bB + (uint32_t)(n*BPAD + kl)*2u);
#pragma unroll
                for (int mt=0; mt<2; mt++){
#pragma unroll
                    for (int s2=0; s2<2; s2++){
                        const int ci = (mt*8 + nt4*2 + s2)*4;
                        mma_f16(acc[ci],acc[ci+1],acc[ci+2],acc[ci+3], ah[mt], bh[s2*2], bh[s2*2+1]);
                        if (useLo)
                            mma_f16(acc[ci],acc[ci+1],acc[ci+2],acc[ci+3], al[mt], bh[s2*2], bh[s2*2+1]);
                    }
                }
            }
        }
        __syncthreads();

        if (idx == 7){
            // h2 = relu(D + bh2) -> fp16 hi/lo back into A smem
#pragma unroll
            for (int mt=0; mt<2; mt++){
#pragma unroll
                for (int nt=0; nt<8; nt++){
                    const int ci = (mt*8 + nt)*4;
                    int rowA = wm*32 + mt*16 + (lane>>2);
                    int col0 = wn*64 + nt*8 + (lane&3)*2;
                    uint32_t hi, lo;
                    split2h(fmaxf(acc[ci+0]+sB2[col0],0.0f), fmaxf(acc[ci+1]+sB2[col0+1],0.0f), hi, lo);
                    *(uint32_t*)(sm + rowA*(KPAD*2) + col0*2) = hi;
                    *(uint32_t*)(sm + A_B + rowA*(KPAD*2) + col0*2) = lo;
                    split2h(fmaxf(acc[ci+2]+sB2[col0],0.0f), fmaxf(acc[ci+3]+sB2[col0+1],0.0f), hi, lo);
                    *(uint32_t*)(sm + (rowA+8)*(KPAD*2) + col0*2) = hi;
                    *(uint32_t*)(sm + A_B + (rowA+8)*(KPAD*2) + col0*2) = lo;
                    acc[ci+0]=0.0f; acc[ci+1]=0.0f; acc[ci+2]=0.0f; acc[ci+3]=0.0f;
                }
            }
            __syncthreads();
        }
    }

    // h3 = relu(D + bh3) -> fp32 smem, then 256->3 reduction
    float* sF = (float*)sm;
#pragma unroll
    for (int mt=0; mt<2; mt++){
#pragma unroll
        for (int nt=0; nt<8; nt++){
            const int ci = (mt*8 + nt)*4;
            int rowA = wm*32 + mt*16 + (lane>>2);
            int col0 = wn*64 + nt*8 + (lane&3)*2;
            sF[rowA*FPAD + col0]       = fmaxf(acc[ci+0]+sB3[col0],   0.0f);
            sF[rowA*FPAD + col0+1]     = fmaxf(acc[ci+1]+sB3[col0+1], 0.0f);
            sF[(rowA+8)*FPAD + col0]   = fmaxf(acc[ci+2]+sB3[col0],   0.0f);
            sF[(rowA+8)*FPAD + col0+1] = fmaxf(acc[ci+3]+sB3[col0+1], 0.0f);
        }
    }
    __syncthreads();

    {
        int row = tid>>2, part = tid&3;
        const float4* rp = (const float4*)(sF + row*FPAD + part*64);
        float a0=0,a1=0,a2=0;
#pragma unroll
        for (int j=0;j<16;j++){
            float4 v = rp[j];
            int cb = part*64 + j*4;
            a0 += v.x*__ldg(&wh4[cb*3+0]) + v.y*__ldg(&wh4[(cb+1)*3+0]) + v.z*__ldg(&wh4[(cb+2)*3+0]) + v.w*__ldg(&wh4[(cb+3)*3+0]);
            a1 += v.x*__ldg(&wh4[cb*3+1]) + v.y*__ldg(&wh4[(cb+1)*3+1]) + v.z*__ldg(&wh4[(cb+2)*3+1]) + v.w*__ldg(&wh4[(cb+3)*3+1]);
            a2 += v.x*__ldg(&wh4[cb*3+2]) + v.y*__ldg(&wh4[(cb+1)*3+2]) + v.z*__ldg(&wh4[(cb+2)*3+2]) + v.w*__ldg(&wh4[(cb+3)*3+2]);
        }
#pragma unroll
        for (int o=1;o<4;o<<=1){
            a0 += __shfl_xor_sync(0xffffffffu, a0, o);
            a1 += __shfl_xor_sync(0xffffffffu, a1, o);
            a2 += __shfl_xor_sync(0xffffffffu, a2, o);
        }
        if (part==0 && row < valid){
            int slot = base + row;
            int q = sQ[row];
            g_pred[       q] = a0 + sBh4[0] + g_resid[slot*3+0];
            g_pred[  NQ + q] = a1 + sBh4[1] + g_resid[slot*3+1];
            g_pred[2*NQ + q] = a2 + sBh4[2] + g_resid[slot*3+2];
        }
    }
}

// ---------------- refinement: 16x16 tile + halo in smem ----------------
__global__ __launch_bounds__(256) void refine_kernel(float* __restrict__ out)
{
    __shared__ float sp[3][18][18];
    __shared__ int   sf[18][18];
    const int tid = threadIdx.x;
    const int bx = blockIdx.x*16, by = blockIdx.y*16;

    for (int i=tid; i<324; i+=256){
        int lr_ = i/18, lc = i - lr_*18;
        int gr = min(max(by + lr_ - 1, 0), HHR-1);
        int gc = min(max(bx + lc - 1, 0), HHR-1);
        int qq = gr*HHR + gc;
        sf[lr_][lc]    = g_flag[qq];
        sp[0][lr_][lc] = g_pred[qq];
        sp[1][lr_][lc] = g_pred[NQ+qq];
        sp[2][lr_][lc] = g_pred[2*NQ+qq];
    }
    __syncthreads();

    const int ty = tid>>4, tx = tid&15;
    const int r = by+ty, s = bx+tx;
    const int q = r*HHR + s;
    float p0 = sp[0][ty+1][tx+1], p1 = sp[1][ty+1][tx+1], p2 = sp[2][ty+1][tx+1];
    if (r>0 && r<HHR-1 && s>0 && s<HHR-1 && sf[ty+1][tx+1]==0){
        int fs = 0;
#pragma unroll
        for (int dy=0;dy<3;dy++)
#pragma unroll
            for (int dx=0;dx<3;dx++)
                fs += sf[ty+dy][tx+dx];
        if (fs > 0){
            float s0=0,s1=0,s2=0;
#pragma unroll
            for (int dy=0;dy<3;dy++)
#pragma unroll
                for (int dx=0;dx<3;dx++){
                    s0 += sp[0][ty+dy][tx+dx];
                    s1 += sp[1][ty+dy][tx+dx];
                    s2 += sp[2][ty+dy][tx+dx];
                }
            p0 = s0/9.0f; p1 = s1/9.0f; p2 = s2/9.0f;
        }
    }
    out[q*3+0] = p0;
    out[q*3+1] = p1;
    out[q*3+2] = p2;
}

// ---------------- launch ----------------
extern "C" void kernel_launch(void* const* d_in, const int* in_sizes, int n_in,
                              void* d_out, int out_size)
{
    (void)in_sizes; (void)n_in;
    const float* lr  =(const float*)d_in[0];
    const float* cell=(const float*)d_in[2];
    const float* ew1 =(const float*)d_in[3];
    const float* eb1 =(const float*)d_in[4];
    const float* ew2 =(const float*)d_in[5];
    const float* eb2 =(const float*)d_in[6];
    const float* ew3 =(const float*)d_in[7];
    const float* eb3 =(const float*)d_in[8];
    const float* wh1 =(const float*)d_in[9];
    const float* bh1 =(const float*)d_in[10];
    const float* wh2 =(const float*)d_in[11];
    const float* bh2 =(const float*)d_in[12];
    const float* wh3 =(const float*)d_in[13];
    const float* bh3 =(const float*)d_in[14];
    const float* wh4 =(const float*)d_in[15];
    const float* bh4 =(const float*)d_in[16];
    const float* wl1 =(const float*)d_in[17];
    const float* bl1 =(const float*)d_in[18];
    const float* wl2 =(const float*)d_in[19];
    const float* bl2 =(const float*)d_in[20];
    const float* wc1 =(const float*)d_in[21];
    const float* bc1 =(const float*)d_in[22];
    const float* wc2 =(const float*)d_in[23];
    const float* bc2 =(const float*)d_in[24];
    float* out = (float*)d_out;

    float *b1, *b2, *feat;
    cudaGetSymbolAddress((void**)&b1,   g_b1);
    cudaGetSymbolAddress((void**)&b2,   g_b2);
    cudaGetSymbolAddress((void**)&feat, g_feat);

    // dynamic smem: sIn[2][CH][3][104] + sW[2][16][CH][9]
    const int sm3  = 2*3*3*104*4  + 2*16*3*9*4;    // 7488 + 3456 = 10944
    const int sm64 = 2*16*3*104*4 + 2*16*16*9*4;   // 39936 + 18432 = 58368
    cudaFuncSetAttribute(conv3x3_kernel<3 ,true >, cudaFuncAttributeMaxDynamicSharedMemorySize, sm3);
    cudaFuncSetAttribute(conv3x3_kernel<64,true >, cudaFuncAttributeMaxDynamicSharedMemorySize, sm64);
    cudaFuncSetAttribute(conv3x3_kernel<64,false>, cudaFuncAttributeMaxDynamicSharedMemorySize, sm64);
    cudaFuncSetAttribute(gemm_kernel, cudaFuncAttributeMaxDynamicSharedMemorySize, DSM2);

    precompute_kernel<<<1,256>>>(wh1,bh1,wc1,bc1,wl1,bl1,cell);
    wsplit_kernel<<<512,256>>>(wh2, wh3);
    conv3x3_kernel<3 ,true ><<<dim3(96,4),256,sm3 >>>(lr, ew1, eb1, b1);
    conv3x3_kernel<64,true ><<<dim3(96,4),256,sm64>>>(b1, ew2, eb2, b2);
    conv3x3_kernel<64,false><<<dim3(96,4),256,sm64>>>(b2, ew3, eb3, feat);
    front_kernel<<<384,256>>>(wc1, wl1, wh1);
    mlpB_kernel<<<2304,256>>>(lr, wc2, bc2, wl2, bl2, out, out_size);
    gemm_kernel<<<NT2,256,DSM2>>>(bh2, bh3, wh4, bh4);
    refine_kernel<<<dim3(24,24),256>>>(out);
}

// round 11
// speedup vs baseline: 1.2779x; 1.1792x over previous
#include <cuda_runtime.h>
#include <cuda_fp16.h>
#include <math.h>
#include <stdint.h>

#define HLR   96
#define HWLR  9216
#define HHR   384
#define NQ    147456
#define TR    64                   // GEMM tile rows
#define NT2   (NQ/TR)              // 2304 tiles
#define KPAD  264                  // A smem row pad (fp16 elems)
#define BPAD  40                   // B smem row pad (fp16 elems)
#define FPAD  260                  // h3 fp32 smem row pad
#define A_B   (TR*KPAD*2)          // 33792 bytes (single fp16 component)
#define B_COMP (256*BPAD*2)        // 20480 bytes per B stage
#define DSM2  (A_B + 2*B_COMP)     // 74752

// ---------------- static device scratch ----------------
__device__ float g_b1[64*HWLR];
__device__ float g_b2[64*HWLR];
__device__ float g_feat[64*HWLR];
__device__ float g_H[(size_t)HWLR*384];
__device__ float g_offH[16*256];
__device__ float g_offC[16*64];
__device__ float g_offL[16*64];
__device__ float g_pred[3*NQ];
__device__ int   g_flag[NQ];
__device__ int   g_cnt;
__device__ int   g_qidx[NQ];
__device__ float g_resid[3*NQ];
__device__ __align__(16) __half g_W2h[65536];   // [n][k] fp16
__device__ __align__(16) __half g_W3h[65536];

// ---------------- helpers ----------------
__device__ __forceinline__ uint32_t smem_u32(const void* p){
    uint32_t a;
    asm("{ .reg .u64 t; cvta.to.shared.u64 t, %1; cvt.u32.u64 %0, t; }" : "=r"(a) : "l"(p));
    return a;
}
__device__ __forceinline__ void ldsm4(uint32_t r[4], uint32_t addr){
    asm volatile("ldmatrix.sync.aligned.m8n8.x4.shared.b16 {%0,%1,%2,%3}, [%4];"
        : "=r"(r[0]),"=r"(r[1]),"=r"(r[2]),"=r"(r[3]) : "r"(addr));
}
__device__ __forceinline__ void mma_f16(float& c0, float& c1, float& c2, float& c3,
    const uint32_t a[4], uint32_t b0, uint32_t b1){
    asm volatile("mma.sync.aligned.m16n8k16.row.col.f32.f16.f16.f32 "
        "{%0,%1,%2,%3}, {%4,%5,%6,%7}, {%8,%9}, {%0,%1,%2,%3};"
        : "+f"(c0),"+f"(c1),"+f"(c2),"+f"(c3)
        : "r"(a[0]),"r"(a[1]),"r"(a[2]),"r"(a[3]),"r"(b0),"r"(b1));
}
__device__ __forceinline__ uint32_t pack2h(float v0, float v1){
    __half h0=__float2half(v0), h1=__float2half(v1);
    return (uint32_t)__half_as_ushort(h0) | ((uint32_t)__half_as_ushort(h1)<<16);
}
__device__ __forceinline__ void cp16(uint32_t dst, const void* src){
    asm volatile("cp.async.cg.shared.global [%0], [%1], 16;" :: "r"(dst), "l"(src));
}

// ---------------- merged prep: weight fp16 convert (blocks 0..511) + offsets (block 512) ----------------
__global__ void prep_kernel(const float* __restrict__ wh2, const float* __restrict__ wh3,
                            const float* __restrict__ wh1, const float* __restrict__ bh1,
                            const float* __restrict__ wc1, const float* __restrict__ bc1,
                            const float* __restrict__ wl1, const float* __restrict__ bl1,
                            const float* __restrict__ cell)
{
    if (blockIdx.x < 512){
        int idx = blockIdx.x*256 + threadIdx.x;
        int layer = idx >> 16;
        int e = idx & 65535;
        int k = e >> 8, n = e & 255;
        const float* w = layer ? wh3 : wh2;
        float v = w[k*256 + n];
        if (layer) g_W3h[(uint32_t)n*256u + k] = __float2half(v);
        else       g_W2h[(uint32_t)n*256u + k] = __float2half(v);
        return;
    }
    int t = threadIdx.x;
    if (t==0) g_cnt = 0;
    float rcy = cell[0]*96.0f, rcx = cell[1]*96.0f;
    float rel[4];
#pragma unroll
    for (int m=0;m<4;m++){
        float cy = -1.0f + (2.0f*(float)m + 1.0f)/384.0f;
        float fy = -1.0f + 1.0f/96.0f;
        rel[m] = (cy - fy)*96.0f;
    }
    for (int m=0;m<16;m++){
        float ry = rel[m>>2], rx = rel[m&3];
        g_offH[m*256+t] = ry*wh1[64*256+t] + rx*wh1[65*256+t]
                        + rcy*wh1[66*256+t] + rcx*wh1[67*256+t] + bh1[t];
        if (t < 64){
            g_offC[m*64+t] = ry*wc1[64*64+t] + rx*wc1[65*64+t]
                           + rcy*wc1[66*64+t] + rcx*wc1[67*64+t] + bc1[t];
            g_offL[m*64+t] = ry*wl1[64*64+t] + rx*wl1[65*64+t]
                           + rcy*wl1[66*64+t] + rcx*wl1[67*64+t] + bl1[t];
        }
    }
}

// ---------------- 3x3 SAME conv; double-buffered input AND weight chunks ----------------
template<int IC, bool RELU>
__global__ __launch_bounds__(256) void conv3x3_kernel(
    const float* __restrict__ in, const float* __restrict__ w,
    const float* __restrict__ bias, float* __restrict__ out)
{
    constexpr int CH = (IC < 16) ? IC : 16;
    constexpr int NCHUNK = IC / CH;
    constexpr int WCH = 16*CH*9;
    extern __shared__ __align__(16) char csm[];
    float* sIn = (float*)csm;
    float* sW  = (float*)(csm + (size_t)2*CH*3*104*4);

    const int y   = blockIdx.x;
    const int ocg = blockIdx.y;
    const int tid = threadIdx.x;
    const int ol  = tid >> 4;
    const int oc  = ocg*16 + ol;
    const int x0  = (tid & 15) * 6;

    for (int i=tid; i<2*CH*3; i+=256){
        int b = i/(CH*3), rr = i - b*(CH*3);
        int ic = rr/3, ry = rr - ic*3;
        float* row = sIn + (((b*CH+ic)*3+ry)*104);
        row[3] = 0.0f; row[100] = 0.0f;
        int yy = y + ry - 1;
        if (yy < 0 || yy >= 96){
            for (int x=4; x<100; x++) row[x] = 0.0f;
        }
    }

    auto stage_in = [&](int cc, int b){
        for (int i=tid; i<CH*3*24; i+=256){
            int ic = i/72, r = i - ic*72, ry = r/24, c4 = r - ry*24;
            int yy = y + ry - 1;
            if (yy>=0 && yy<96)
                cp16(smem_u32(sIn + (((b*CH+ic)*3+ry)*104) + 4 + c4*4),
                     in + (size_t)(cc*CH+ic)*HWLR + yy*96 + c4*4);
        }
    };
    auto stage_w = [&](int cc, int b){
        if (IC >= 16){
            for (int i=tid; i<16*36; i+=256){
                int o = i/36, q = i - o*36;
                const float* src = w + ((size_t)(ocg*16+o)*IC + cc*CH)*9 + q*4;
                cp16(smem_u32(sW + b*WCH + o*(CH*9) + q*4), src);
            }
        } else {
            for (int i=tid; i<WCH; i+=256)
                sW[b*WCH + i] = w[(size_t)ocg*16*IC*9 + i];
        }
    };

    stage_in(0, 0);
    stage_w(0, 0);
    asm volatile("cp.async.commit_group;");

    float acc[6];
#pragma unroll
    for (int j=0;j<6;j++) acc[j]=0.0f;

    for (int c=0; c<NCHUNK; c++){
        __syncthreads();
        if (c+1 < NCHUNK){
            int b = (c+1)&1;
            stage_in(c+1, b);
            stage_w(c+1, b);
            asm volatile("cp.async.commit_group;");
            asm volatile("cp.async.wait_group 1;");
        } else {
            asm volatile("cp.async.wait_group 0;");
        }
        __syncthreads();

        const int b = c&1;
#pragma unroll 2
        for (int ic=0; ic<CH; ic++){
            const float* r0p = sIn + (((b*CH+ic)*3+0)*104) + x0 + 3;
            const float* r1p = r0p + 104;
            const float* r2p = r1p + 104;
            float r0[8],r1[8],r2[8];
#pragma unroll
            for (int d=0;d<8;d++){ r0[d]=r0p[d]; r1[d]=r1p[d]; r2[d]=r2p[d]; }
            const float* wp = sW + b*WCH + (ol*CH + ic)*9;
            float w00=wp[0], w01=wp[1], w02=wp[2];
            float w10=wp[3], w11=wp[4], w12=wp[5];
            float w20=wp[6], w21=wp[7], w22=wp[8];
#pragma unroll
            for (int j=0;j<6;j++){
                acc[j] += w00*r0[j]+w01*r0[j+1]+w02*r0[j+2]
                        + w10*r1[j]+w11*r1[j+1]+w12*r1[j+2]
                        + w20*r2[j]+w21*r2[j+1]+w22*r2[j+2];
            }
        }
    }
    float b = __ldg(bias+oc);
#pragma unroll
    for (int j=0;j<6;j++){
        float v = acc[j]+b;
        if (RELU) v = fmaxf(v,0.0f);
        out[oc*HWLR + y*96 + x0 + j] = v;
    }
}

// ---------------- front GEMM: g_H[p][384] = feat[p][64] x [wc1|wl1|wh1] ----------------
__global__ __launch_bounds__(256) void front_kernel(
    const float* __restrict__ wc1, const float* __restrict__ wl1, const float* __restrict__ wh1)
{
    __shared__ float sF[64][25];
    __shared__ float sW[16][385];
    const int tid = threadIdx.x;
    const int P0  = blockIdx.x*24;
    const int txp = tid & 3;
    const int txc = tid >> 2;

    for (int i=tid; i<64*24; i+=256){
        int c = i/24, pl = i - c*24;
        sF[c][pl] = g_feat[c*HWLR + P0 + pl];
    }

    float acc[6][6];
#pragma unroll
    for (int i=0;i<6;i++)
#pragma unroll
        for (int j=0;j<6;j++) acc[i][j]=0.0f;

    for (int c0=0; c0<64; c0+=16){
        __syncthreads();
        for (int i=tid; i<16*384; i+=256){
            int cc = i/384, n = i - cc*384;
            int c = c0 + cc;
            float w;
            if (n < 64)        w = wc1[c*64 + n];
            else if (n < 128)  w = wl1[c*64 + (n-64)];
            else               w = wh1[c*256 + (n-128)];
            sW[cc][n] = w;
        }
        __syncthreads();
#pragma unroll
        for (int cc=0; cc<16; cc++){
            float f[6], w[6];
#pragma unroll
            for (int j=0;j<6;j++) f[j] = sF[c0+cc][txp*6+j];
#pragma unroll
            for (int i=0;i<6;i++) w[i] = sW[cc][txc*6+i];
#pragma unroll
            for (int i=0;i<6;i++)
#pragma unroll
                for (int j=0;j<6;j++) acc[i][j] += w[i]*f[j];
        }
    }
#pragma unroll
    for (int j=0;j<6;j++)
#pragma unroll
        for (int i=0;i<6;i++)
            g_H[(size_t)(P0 + txp*6 + j)*384 + txc*6 + i] = acc[i][j];
}

// ---------------- mlpB: classify/light/compact; 4 px per block ----------------
__global__ __launch_bounds__(256) void mlpB_kernel(
    const float* __restrict__ lr,
    const float* __restrict__ wc2, const float* __restrict__ bc2,
    const float* __restrict__ wl2, const float* __restrict__ bl2,
    float* __restrict__ out, int out_size)
{
    __shared__ float sHc[4][64];
    __shared__ float sHl[4][64];
    __shared__ float sPredL[4][16][3];
    __shared__ int sFlag[4][16];
    __shared__ int sInv[4][16];
    __shared__ int sMcount[4];
    __shared__ int sBase[4];

    const int tid = threadIdx.x;
    const int p0  = blockIdx.x*4;

    {
        int pp = tid>>6, c = tid&63;
        sHc[pp][c] = g_H[(size_t)(p0+pp)*384 + c];
        sHl[pp][c] = g_H[(size_t)(p0+pp)*384 + 64 + c];
    }
    __syncthreads();

    {
        int wid = tid>>5, lane = tid&31;
#pragma unroll
        for (int i=0;i<8;i++){
            int qq = wid*8 + i;
            int pp = qq>>4, m = qq&15;
            float l0=0,l1=0,q0=0,q1=0,q2=0;
#pragma unroll
            for (int hh=0;hh<2;hh++){
                int t = lane + hh*32;
                float hc = fmaxf(sHc[pp][t] + g_offC[m*64+t], 0.0f);
                l0 += hc*__ldg(&wc2[t*2+0]);
                l1 += hc*__ldg(&wc2[t*2+1]);
                float hl = fmaxf(sHl[pp][t] + g_offL[m*64+t], 0.0f);
                q0 += hl*__ldg(&wl2[t*3+0]);
                q1 += hl*__ldg(&wl2[t*3+1]);
                q2 += hl*__ldg(&wl2[t*3+2]);
            }
#pragma unroll
            for (int o=16;o>0;o>>=1){
                l0+=__shfl_xor_sync(0xffffffffu,l0,o);
                l1+=__shfl_xor_sync(0xffffffffu,l1,o);
                q0+=__shfl_xor_sync(0xffffffffu,q0,o);
                q1+=__shfl_xor_sync(0xffffffffu,q1,o);
                q2+=__shfl_xor_sync(0xffffffffu,q2,o);
            }
            if (lane==0){
                l0 += __ldg(&bc2[0]); l1 += __ldg(&bc2[1]);
                sFlag[pp][m] = (l1 > l0) ? 1 : 0;
                sPredL[pp][m][0] = q0 + __ldg(&bl2[0]);
                sPredL[pp][m][1] = q1 + __ldg(&bl2[1]);
                sPredL[pp][m][2] = q2 + __ldg(&bl2[2]);
            }
        }
    }
    __syncthreads();

    if (tid < 4){
        int c=0;
        for (int m=0;m<16;m++){
            sInv[tid][m] = -1;
            if (sFlag[tid][m]){ sInv[tid][m]=c; c++; }
        }
        sMcount[tid] = c;
    }
    __syncthreads();
    if (tid==0){
        int tot = sMcount[0]+sMcount[1]+sMcount[2]+sMcount[3];
        int b = tot ? atomicAdd(&g_cnt, tot) : 0;
        sBase[0]=b;
        sBase[1]=b+sMcount[0];
        sBase[2]=sBase[1]+sMcount[1];
        sBase[3]=sBase[2]+sMcount[2];
    }
    __syncthreads();

    if (tid < 64){
        int pp = tid>>4, mm = tid&15;
        int p = p0+pp, py = p/96, px = p - py*96;
        int r = py*4 + (mm>>2), s = px*4 + (mm&3);
        int q = r*HHR + s;
        g_flag[q] = sFlag[pp][mm];
        if (out_size >= 4*NQ) out[3*NQ + q] = (float)sFlag[pp][mm];
    }

    if (tid < 192){
        int pp = tid/48, r3 = tid - pp*48;
        int m = r3/3, j = r3 - m*3;
        int p = p0+pp, py = p/96, px = p - py*96;
        int r = py*4 + (m>>2), s = px*4 + (m&3);
        int q = r*HHR + s;
        float cy = -1.0f + (2.0f*(float)r + 1.0f)/384.0f;
        float cx = -1.0f + (2.0f*(float)s + 1.0f)/384.0f;
        float fy = fminf(fmaxf((cy+1.0f)*48.0f - 0.5f, 0.0f), 95.0f);
        float fx = fminf(fmaxf((cx+1.0f)*48.0f - 0.5f, 0.0f), 95.0f);
        float y0f = floorf(fy), x0f = floorf(fx);
        float wy = fy - y0f, wx = fx - x0f;
        int y0 = (int)y0f, x0 = (int)x0f;
        int y1 = min(y0+1,95), x1 = min(x0+1,95);
        const float* img = lr + j*HWLR;
        float v00=__ldg(&img[y0*96+x0]), v01=__ldg(&img[y0*96+x1]);
        float v10=__ldg(&img[y1*96+x0]), v11=__ldg(&img[y1*96+x1]);
        float resid = v00*(1.0f-wy)*(1.0f-wx) + v01*(1.0f-wy)*wx
                    + v10*wy*(1.0f-wx)       + v11*wy*wx;
        if (sFlag[pp][m]==0){
            g_pred[j*NQ + q] = sPredL[pp][m][j] + resid;
        } else {
            int slot = sBase[pp] + sInv[pp][m];
            g_resid[slot*3 + j] = resid;
            if (j==0) g_qidx[slot] = q;
        }
    }
}

// ---------------- B stage (fp16) via cp.async ----------------
__device__ __forceinline__ void stage_B(int tid, uint32_t bbase,
    const __half* __restrict__ Wh, int kc)
{
    for (int i=tid;i<1024;i+=256){
        int n=i>>2, c4=i&3;
        cp16(bbase + (uint32_t)n*(BPAD*2) + (uint32_t)c4*16, Wh + n*256 + kc*32 + c4*8);
    }
    asm volatile("cp.async.commit_group;");
}

// ---------------- GEMM: heavy layers 1(build)+2+3+4; single fp16 product per layer ----------------
__global__ __launch_bounds__(256, 2) void gemm_kernel(
    const float* __restrict__ bh2, const float* __restrict__ bh3,
    const float* __restrict__ wh4, const float* __restrict__ bh4)
{
    extern __shared__ unsigned char sm[];
    __shared__ float sB2[256], sB3[256], sBh4[4];
    __shared__ int sQ[TR], sMi[TR], sPi[TR];
    __shared__ int s_cnt;

    const int tid = threadIdx.x, wid = tid>>5, lane = tid&31;
    if (tid==0) s_cnt = g_cnt;
    __syncthreads();
    const int cnt  = s_cnt;
    const int base = blockIdx.x*TR;
    if (base >= cnt) return;
    const int valid = min(TR, cnt - base);

    sB2[tid]=__ldg(&bh2[tid]); sB3[tid]=__ldg(&bh3[tid]);
    if (tid<3) sBh4[tid]=__ldg(&bh4[tid]);
    if (tid < valid){
        int q = g_qidx[base+tid];
        int r = q/HHR, s = q - r*HHR;
        sQ[tid]  = q;
        sMi[tid] = (r&3)*4 + (s&3);
        sPi[tid] = (r>>2)*96 + (s>>2);
    }
    __syncthreads();

    // build A (h1 fp16) from g_H + g_offH
    for (int i=0;i<valid;i++){
        int m = sMi[i], p = sPi[i];
        float v = fmaxf(g_H[(size_t)p*384 + 128 + tid] + g_offH[m*256+tid], 0.0f);
        *(unsigned short*)(sm + i*(KPAD*2) + tid*2) = __half_as_ushort(__float2half(v));
    }

    const int wm = wid & 1;      // 2 row groups of 32
    const int wn = wid >> 1;     // 4 col groups of 64
    const uint32_t smA = smem_u32(sm);
    const uint32_t smB = smA + A_B;

    float acc[64];
#pragma unroll
    for (int i=0;i<64;i++) acc[i]=0.0f;

    stage_B(tid, smB, g_W2h, 0);

    for (int idx=0; idx<16; idx++){
        if (idx < 15){
            int nx = idx+1;
            stage_B(tid, smB + (uint32_t)(nx&1)*B_COMP, (nx&8)?g_W3h:g_W2h, nx&7);
            asm volatile("cp.async.wait_group 1;");
        } else {
            asm volatile("cp.async.wait_group 0;");
        }
        __syncthreads();

        const int kc = idx & 7;
        const uint32_t bB = smB + (uint32_t)(idx&1)*B_COMP;
#pragma unroll
        for (int kk=0; kk<32; kk+=16){
            uint32_t ah[2][4];
#pragma unroll
            for (int mt=0; mt<2; mt++){
                int r = wm*32 + mt*16 + (lane&7) + ((lane>>3)&1)*8;
                int kcol = kc*32 + kk + (lane>>4)*8;
                ldsm4(ah[mt], smA + (uint32_t)(r*KPAD + kcol)*2u);
            }
#pragma unroll
            for (int nt4=0; nt4<4; nt4++){
                int n = wn*64 + nt4*16 + (lane>>4)*8 + (lane&7);
                int kl = kk + ((lane>>3)&1)*8;
                uint32_t bh[4];
                ldsm4(bh, bB + (uint32_t)(n*BPAD + kl)*2u);
#pragma unroll
                for (int mt=0; mt<2; mt++){
#pragma unroll
                    for (int s2=0; s2<2; s2++){
                        const int ci = (mt*8 + nt4*2 + s2)*4;
                        mma_f16(acc[ci],acc[ci+1],acc[ci+2],acc[ci+3], ah[mt], bh[s2*2], bh[s2*2+1]);
                    }
                }
            }
        }
        __syncthreads();

        if (idx == 7){
            // h2 = relu(D + bh2) -> fp16 back into A smem
#pragma unroll
            for (int mt=0; mt<2; mt++){
#pragma unroll
                for (int nt=0; nt<8; nt++){
                    const int ci = (mt*8 + nt)*4;
                    int rowA = wm*32 + mt*16 + (lane>>2);
                    int col0 = wn*64 + nt*8 + (lane&3)*2;
                    *(uint32_t*)(sm + rowA*(KPAD*2) + col0*2) =
                        pack2h(fmaxf(acc[ci+0]+sB2[col0],0.0f), fmaxf(acc[ci+1]+sB2[col0+1],0.0f));
                    *(uint32_t*)(sm + (rowA+8)*(KPAD*2) + col0*2) =
                        pack2h(fmaxf(acc[ci+2]+sB2[col0],0.0f), fmaxf(acc[ci+3]+sB2[col0+1],0.0f));
                    acc[ci+0]=0.0f; acc[ci+1]=0.0f; acc[ci+2]=0.0f; acc[ci+3]=0.0f;
                }
            }
            __syncthreads();
        }
    }

    // h3 = relu(D + bh3) -> fp32 smem (overwrites A+B regions; B is dead), then 256->3
    float* sF = (float*)sm;
#pragma unroll
    for (int mt=0; mt<2; mt++){
#pragma unroll
        for (int nt=0; nt<8; nt++){
            const int ci = (mt*8 + nt)*4;
            int rowA = wm*32 + mt*16 + (lane>>2);
            int col0 = wn*64 + nt*8 + (lane&3)*2;
            sF[rowA*FPAD + col0]       = fmaxf(acc[ci+0]+sB3[col0],   0.0f);
            sF[rowA*FPAD + col0+1]     = fmaxf(acc[ci+1]+sB3[col0+1], 0.0f);
            sF[(rowA+8)*FPAD + col0]   = fmaxf(acc[ci+2]+sB3[col0],   0.0f);
            sF[(rowA+8)*FPAD + col0+1] = fmaxf(acc[ci+3]+sB3[col0+1], 0.0f);
        }
    }
    __syncthreads();

    {
        int row = tid>>2, part = tid&3;
        const float4* rp = (const float4*)(sF + row*FPAD + part*64);
        float a0=0,a1=0,a2=0;
#pragma unroll
        for (int j=0;j<16;j++){
            float4 v = rp[j];
            int cb = part*64 + j*4;
            a0 += v.x*__ldg(&wh4[cb*3+0]) + v.y*__ldg(&wh4[(cb+1)*3+0]) + v.z*__ldg(&wh4[(cb+2)*3+0]) + v.w*__ldg(&wh4[(cb+3)*3+0]);
            a1 += v.x*__ldg(&wh4[cb*3+1]) + v.y*__ldg(&wh4[(cb+1)*3+1]) + v.z*__ldg(&wh4[(cb+2)*3+1]) + v.w*__ldg(&wh4[(cb+3)*3+1]);
            a2 += v.x*__ldg(&wh4[cb*3+2]) + v.y*__ldg(&wh4[(cb+1)*3+2]) + v.z*__ldg(&wh4[(cb+2)*3+2]) + v.w*__ldg(&wh4[(cb+3)*3+2]);
        }
#pragma unroll
        for (int o=1;o<4;o<<=1){
            a0 += __shfl_xor_sync(0xffffffffu, a0, o);
            a1 += __shfl_xor_sync(0xffffffffu, a1, o);
            a2 += __shfl_xor_sync(0xffffffffu, a2, o);
        }
        if (part==0 && row < valid){
            int slot = base + row;
            int q = sQ[row];
            g_pred[       q] = a0 + sBh4[0] + g_resid[slot*3+0];
            g_pred[  NQ + q] = a1 + sBh4[1] + g_resid[slot*3+1];
            g_pred[2*NQ + q] = a2 + sBh4[2] + g_resid[slot*3+2];
        }
    }
}

// ---------------- refinement: 16x16 tile + halo in smem ----------------
__global__ __launch_bounds__(256) void refine_kernel(float* __restrict__ out)
{
    __shared__ float sp[3][18][18];
    __shared__ int   sf[18][18];
    const int tid = threadIdx.x;
    const int bx = blockIdx.x*16, by = blockIdx.y*16;

    for (int i=tid; i<324; i+=256){
        int lr_ = i/18, lc = i - lr_*18;
        int gr = min(max(by + lr_ - 1, 0), HHR-1);
        int gc = min(max(bx + lc - 1, 0), HHR-1);
        int qq = gr*HHR + gc;
        sf[lr_][lc]    = g_flag[qq];
        sp[0][lr_][lc] = g_pred[qq];
        sp[1][lr_][lc] = g_pred[NQ+qq];
        sp[2][lr_][lc] = g_pred[2*NQ+qq];
    }
    __syncthreads();

    const int ty = tid>>4, tx = tid&15;
    const int r = by+ty, s = bx+tx;
    const int q = r*HHR + s;
    float p0 = sp[0][ty+1][tx+1], p1 = sp[1][ty+1][tx+1], p2 = sp[2][ty+1][tx+1];
    if (r>0 && r<HHR-1 && s>0 && s<HHR-1 && sf[ty+1][tx+1]==0){
        int fs = 0;
#pragma unroll
        for (int dy=0;dy<3;dy++)
#pragma unroll
            for (int dx=0;dx<3;dx++)
                fs += sf[ty+dy][tx+dx];
        if (fs > 0){
            float s0=0,s1=0,s2=0;
#pragma unroll
            for (int dy=0;dy<3;dy++)
#pragma unroll
                for (int dx=0;dx<3;dx++){
                    s0 += sp[0][ty+dy][tx+dx];
                    s1 += sp[1][ty+dy][tx+dx];
                    s2 += sp[2][ty+dy][tx+dx];
                }
            p0 = s0/9.0f; p1 = s1/9.0f; p2 = s2/9.0f;
        }
    }
    out[q*3+0] = p0;
    out[q*3+1] = p1;
    out[q*3+2] = p2;
}

// ---------------- launch ----------------
extern "C" void kernel_launch(void* const* d_in, const int* in_sizes, int n_in,
                              void* d_out, int out_size)
{
    (void)in_sizes; (void)n_in;
    const float* lr  =(const float*)d_in[0];
    const float* cell=(const float*)d_in[2];
    const float* ew1 =(const float*)d_in[3];
    const float* eb1 =(const float*)d_in[4];
    const float* ew2 =(const float*)d_in[5];
    const float* eb2 =(const float*)d_in[6];
    const float* ew3 =(const float*)d_in[7];
    const float* eb3 =(const float*)d_in[8];
    const float* wh1 =(const float*)d_in[9];
    const float* bh1 =(const float*)d_in[10];
    const float* wh2 =(const float*)d_in[11];
    const float* bh2 =(const float*)d_in[12];
    const float* wh3 =(const float*)d_in[13];
    const float* bh3 =(const float*)d_in[14];
    const float* wh4 =(const float*)d_in[15];
    const float* bh4 =(const float*)d_in[16];
    const float* wl1 =(const float*)d_in[17];
    const float* bl1 =(const float*)d_in[18];
    const float* wl2 =(const float*)d_in[19];
    const float* bl2 =(const float*)d_in[20];
    const float* wc1 =(const float*)d_in[21];
    const float* bc1 =(const float*)d_in[22];
    const float* wc2 =(const float*)d_in[23];
    const float* bc2 =(const float*)d_in[24];
    float* out = (float*)d_out;

    float *b1, *b2, *feat;
    cudaGetSymbolAddress((void**)&b1,   g_b1);
    cudaGetSymbolAddress((void**)&b2,   g_b2);
    cudaGetSymbolAddress((void**)&feat, g_feat);

    const int sm3  = 2*3*3*104*4  + 2*16*3*9*4;    // 10944
    const int sm64 = 2*16*3*104*4 + 2*16*16*9*4;   // 58368
    cudaFuncSetAttribute(conv3x3_kernel<3 ,true >, cudaFuncAttributeMaxDynamicSharedMemorySize, sm3);
    cudaFuncSetAttribute(conv3x3_kernel<64,true >, cudaFuncAttributeMaxDynamicSharedMemorySize, sm64);
    cudaFuncSetAttribute(conv3x3_kernel<64,false>, cudaFuncAttributeMaxDynamicSharedMemorySize, sm64);
    cudaFuncSetAttribute(gemm_kernel, cudaFuncAttributeMaxDynamicSharedMemorySize, DSM2);

    prep_kernel<<<513,256>>>(wh2, wh3, wh1, bh1, wc1, bc1, wl1, bl1, cell);
    conv3x3_kernel<3 ,true ><<<dim3(96,4),256,sm3 >>>(lr, ew1, eb1, b1);
    conv3x3_kernel<64,true ><<<dim3(96,4),256,sm64>>>(b1, ew2, eb2, b2);
    conv3x3_kernel<64,false><<<dim3(96,4),256,sm64>>>(b2, ew3, eb3, feat);
    front_kernel<<<384,256>>>(wc1, wl1, wh1);
    mlpB_kernel<<<2304,256>>>(lr, wc2, bc2, wl2, bl2, out, out_size);
    gemm_kernel<<<NT2,256,DSM2>>>(bh2, bh3, wh4, bh4);
    refine_kernel<<<dim3(24,24),256>>>(out);
}